// round 1
// baseline (speedup 1.0000x reference)
#include <cuda_runtime.h>
#include <math.h>

#define DMODEL 1024
#define NH     16
#define DKH    64
#define BATCH  2
#define SEQ    2048
#define MROWS  (BATCH*SEQ)        // 4096

// Scratch (static device globals: allocation-free, allowed)
__device__ float g_qkv[3 * BATCH * NH * SEQ * DKH]; // [which][b*NH+h][s][d]  (48 MB)
__device__ float g_attn[MROWS * DMODEL];            // [b*SEQ+s][h*64+d]     (16 MB)

// ---------------------------------------------------------------------------
// SGEMM: C[M,N] = A[M,K] @ B[K,N] + bias.  128x128 tile, BK=8, 256 thr, 8x8 micro.
// MODE 0: epilogue scatters into g_qkv (QKV projection, N=3072)
// MODE 1: A is g_attn, epilogue writes C densely (output projection)
// ---------------------------------------------------------------------------
template<int MODE>
__global__ __launch_bounds__(256)
void sgemm_kernel(const float* __restrict__ A,
                  const float* __restrict__ B,
                  const float* __restrict__ bias,
                  float* __restrict__ C,
                  int M, int N, int K)
{
    __shared__ float As[8][128];
    __shared__ float Bs[8][128];

    const float* Ain = (MODE == 1) ? g_attn : A;

    int tid  = threadIdx.x;
    int rowg = tid >> 4;          // 0..15
    int colg = tid & 15;          // 0..15
    int m0 = blockIdx.y * 128;
    int n0 = blockIdx.x * 128;

    float acc[8][8];
    #pragma unroll
    for (int i = 0; i < 8; i++)
        #pragma unroll
        for (int j = 0; j < 8; j++) acc[i][j] = 0.f;

    int ar = tid >> 1;            // 0..127
    int ac = (tid & 1) * 4;       // 0 or 4
    int br = tid >> 5;            // 0..7
    int bc = (tid & 31) * 4;      // 0..124

    const float* Aptr = Ain + (size_t)(m0 + ar) * K + ac;
    const float* Bptr = B   + (size_t)br * N + n0 + bc;

    for (int kt = 0; kt < K; kt += 8) {
        float4 a = *(const float4*)(Aptr + kt);
        float4 b = *(const float4*)(Bptr + (size_t)kt * N);
        __syncthreads();                    // prev compute done before smem overwrite
        As[ac + 0][ar] = a.x;
        As[ac + 1][ar] = a.y;
        As[ac + 2][ar] = a.z;
        As[ac + 3][ar] = a.w;
        *(float4*)&Bs[br][bc] = b;
        __syncthreads();

        #pragma unroll
        for (int k = 0; k < 8; k++) {
            float4 a0 = *(float4*)&As[k][rowg * 4];
            float4 a1 = *(float4*)&As[k][rowg * 4 + 64];
            float4 b0 = *(float4*)&Bs[k][colg * 4];
            float4 b1 = *(float4*)&Bs[k][colg * 4 + 64];
            float ra[8] = {a0.x, a0.y, a0.z, a0.w, a1.x, a1.y, a1.z, a1.w};
            float rb[8] = {b0.x, b0.y, b0.z, b0.w, b1.x, b1.y, b1.z, b1.w};
            #pragma unroll
            for (int i = 0; i < 8; i++)
                #pragma unroll
                for (int j = 0; j < 8; j++)
                    acc[i][j] += ra[i] * rb[j];
        }
    }

    #pragma unroll
    for (int i = 0; i < 8; i++) {
        int lr  = rowg * 4 + ((i < 4) ? i : 64 + (i - 4));
        int row = m0 + lr;
        #pragma unroll
        for (int j = 0; j < 8; j++) {
            int lc  = colg * 4 + ((j < 4) ? j : 64 + (j - 4));
            int col = n0 + lc;
            float v = acc[i][j] + bias[col];
            if (MODE == 0) {
                // col in [0,3072): which = col/1024, h = (col%1024)/64, d = col%64
                int which = col >> 10;
                int rem   = col & 1023;
                int h     = rem >> 6;
                int d     = rem & 63;
                int bb    = row >> 11;     // /SEQ
                int s     = row & 2047;
                g_qkv[(size_t)which * (BATCH * NH * SEQ * DKH)
                      + (size_t)(bb * NH + h) * (SEQ * DKH)
                      + (size_t)s * DKH + d] = v;
            } else {
                C[(size_t)row * N + col] = v;
            }
        }
    }
}

// ---------------------------------------------------------------------------
// Flash attention: one CTA = 64 query rows of one (b,h). 256 threads, 4x4 micro.
// Tiles of 64 keys; online softmax; P overlays the K smem tile.
// smem: Qs 64x64 | KP 64x68 (padded) | Vs 64x64  = 50176 B (dynamic)
// ---------------------------------------------------------------------------
#define KP_STRIDE 68
#define ATTN_SMEM ((64*64 + 64*KP_STRIDE + 64*64) * 4)

__global__ __launch_bounds__(256)
void attn_kernel()
{
    extern __shared__ float smem[];
    float* Qs = smem;                         // [row][k]  stride 64
    float* KP = smem + 64 * 64;               // [key][k] stride 68; later P [row][key] stride 68
    float* Vs = smem + 64 * 64 + 64 * KP_STRIDE; // [key][d] stride 64

    int tid = threadIdx.x;
    int ty  = tid >> 4;      // 0..15  (row group)
    int tx  = tid & 15;      // 0..15  (col group)

    int qt = blockIdx.x;     // query tile 0..31
    int bh = blockIdx.y;     // 0..31
    int q0 = qt * 64;

    const float* Qg = g_qkv + (size_t)bh * (SEQ * DKH);
    const float* Kg = g_qkv + (size_t)(BATCH * NH + bh) * (SEQ * DKH);
    const float* Vg = g_qkv + (size_t)(2 * BATCH * NH + bh) * (SEQ * DKH);

    // load + pre-scale Q tile (1/sqrt(64) = 0.125)
    {
        int r  = tid >> 4;
        int c4 = (tid & 15) * 4;
        #pragma unroll
        for (int ch = 0; ch < 4; ch++) {
            int row = r + ch * 16;
            float4 q = *(const float4*)(Qg + (size_t)(q0 + row) * DKH + c4);
            q.x *= 0.125f; q.y *= 0.125f; q.z *= 0.125f; q.w *= 0.125f;
            *(float4*)&Qs[row * 64 + c4] = q;
        }
    }

    float4 acc[4];
    float  mi[4], li[4];
    #pragma unroll
    for (int i = 0; i < 4; i++) {
        acc[i] = make_float4(0.f, 0.f, 0.f, 0.f);
        mi[i] = -1e30f;
        li[i] = 0.f;
    }

    __syncthreads();   // Qs visible

    for (int kt = 0; kt < SEQ; kt += 64) {
        // load K, V tiles
        {
            int r  = tid >> 4;
            int c4 = (tid & 15) * 4;
            #pragma unroll
            for (int ch = 0; ch < 4; ch++) {
                int row = r + ch * 16;
                float4 kv = *(const float4*)(Kg + (size_t)(kt + row) * DKH + c4);
                *(float4*)&KP[row * KP_STRIDE + c4] = kv;
                float4 vv = *(const float4*)(Vg + (size_t)(kt + row) * DKH + c4);
                *(float4*)&Vs[row * 64 + c4] = vv;
            }
        }
        __syncthreads();

        // scores s[i][j] = Qs[4ty+i] . K[4tx+j]
        float s[4][4];
        #pragma unroll
        for (int i = 0; i < 4; i++)
            #pragma unroll
            for (int j = 0; j < 4; j++) s[i][j] = 0.f;

        #pragma unroll
        for (int kk = 0; kk < 64; kk += 4) {
            float4 q[4], k4[4];
            #pragma unroll
            for (int i = 0; i < 4; i++) q[i]  = *(float4*)&Qs[(ty * 4 + i) * 64 + kk];
            #pragma unroll
            for (int j = 0; j < 4; j++) k4[j] = *(float4*)&KP[(tx * 4 + j) * KP_STRIDE + kk];
            #pragma unroll
            for (int i = 0; i < 4; i++)
                #pragma unroll
                for (int j = 0; j < 4; j++)
                    s[i][j] += q[i].x * k4[j].x + q[i].y * k4[j].y
                             + q[i].z * k4[j].z + q[i].w * k4[j].w;
        }

        // online softmax update (row reductions across the 16 tx lanes, width-16 shuffles)
        float p[4][4];
        #pragma unroll
        for (int i = 0; i < 4; i++) {
            float tmax = fmaxf(fmaxf(s[i][0], s[i][1]), fmaxf(s[i][2], s[i][3]));
            #pragma unroll
            for (int off = 8; off; off >>= 1)
                tmax = fmaxf(tmax, __shfl_xor_sync(0xffffffffu, tmax, off, 16));
            float nm = fmaxf(mi[i], tmax);
            float al = __expf(mi[i] - nm);
            float rs = 0.f;
            #pragma unroll
            for (int j = 0; j < 4; j++) { p[i][j] = __expf(s[i][j] - nm); rs += p[i][j]; }
            #pragma unroll
            for (int off = 8; off; off >>= 1)
                rs += __shfl_xor_sync(0xffffffffu, rs, off, 16);
            li[i] = li[i] * al + rs;
            mi[i] = nm;
            acc[i].x *= al; acc[i].y *= al; acc[i].z *= al; acc[i].w *= al;
        }

        __syncthreads();   // everyone done reading K from KP

        // write P [row][key] into KP
        #pragma unroll
        for (int i = 0; i < 4; i++)
            *(float4*)&KP[(ty * 4 + i) * KP_STRIDE + tx * 4] =
                make_float4(p[i][0], p[i][1], p[i][2], p[i][3]);
        __syncthreads();

        // acc += P @ V   (thread: rows 4ty+i, dims 4tx..4tx+3)
        #pragma unroll
        for (int jj = 0; jj < 64; jj += 4) {
            float4 p4[4], v4[4];
            #pragma unroll
            for (int i = 0; i < 4; i++) p4[i] = *(float4*)&KP[(ty * 4 + i) * KP_STRIDE + jj];
            #pragma unroll
            for (int j = 0; j < 4; j++) v4[j] = *(float4*)&Vs[(jj + j) * 64 + tx * 4];
            #pragma unroll
            for (int i = 0; i < 4; i++) {
                acc[i].x += p4[i].x * v4[0].x + p4[i].y * v4[1].x + p4[i].z * v4[2].x + p4[i].w * v4[3].x;
                acc[i].y += p4[i].x * v4[0].y + p4[i].y * v4[1].y + p4[i].z * v4[2].y + p4[i].w * v4[3].y;
                acc[i].z += p4[i].x * v4[0].z + p4[i].y * v4[1].z + p4[i].z * v4[2].z + p4[i].w * v4[3].z;
                acc[i].w += p4[i].x * v4[0].w + p4[i].y * v4[1].w + p4[i].z * v4[2].w + p4[i].w * v4[3].w;
            }
        }
        __syncthreads();   // before next tile overwrites KP/Vs
    }

    // epilogue: O[b, s, h*64 + d] = acc / l
    int bb = bh >> 4;
    int h  = bh & 15;
    #pragma unroll
    for (int i = 0; i < 4; i++) {
        float inv = 1.0f / li[i];
        int row = q0 + ty * 4 + i;
        float4 o = make_float4(acc[i].x * inv, acc[i].y * inv, acc[i].z * inv, acc[i].w * inv);
        *(float4*)(g_attn + (size_t)(bb * SEQ + row) * DMODEL + h * DKH + tx * 4) = o;
    }
}

// ---------------------------------------------------------------------------
extern "C" void kernel_launch(void* const* d_in, const int* in_sizes, int n_in,
                              void* d_out, int out_size)
{
    const float* x     = (const float*)d_in[0];
    const float* Wqkv  = (const float*)d_in[1];
    const float* bqkv  = (const float*)d_in[2];
    const float* Wout  = (const float*)d_in[3];
    const float* bout  = (const float*)d_in[4];
    float* out = (float*)d_out;

    // 1) QKV projection + scatter into [3][bh][s][d]
    sgemm_kernel<0><<<dim3(3 * DMODEL / 128, MROWS / 128), 256>>>(
        x, Wqkv, bqkv, nullptr, MROWS, 3 * DMODEL, DMODEL);

    // 2) flash attention -> g_attn [b*s][h*64+d]
    cudaFuncSetAttribute(attn_kernel, cudaFuncAttributeMaxDynamicSharedMemorySize, ATTN_SMEM);
    attn_kernel<<<dim3(SEQ / 64, BATCH * NH), 256, ATTN_SMEM>>>();

    // 3) output projection
    sgemm_kernel<1><<<dim3(DMODEL / 128, MROWS / 128), 256>>>(
        nullptr, Wout, bout, out, MROWS, DMODEL, DMODEL);
}